// round 3
// baseline (speedup 1.0000x reference)
#include <cuda_runtime.h>
#include <cuda_fp16.h>
#include <cstdint>
#include <math.h>

#define VV   32000
#define EE   512
#define HH   512
#define MIDD 128
#define BB   16
#define SS   512

// scratch (device globals: no runtime allocation allowed)
__device__ float  g_Zx[BB * SS * MIDD];     // 4 MB
__device__ __half g_out16[BB * SS * EE];    // 8 MB
__device__ __half g_embed16[VV * EE];       // 32 MB

// ---------------------------------------------------------------- helpers
__device__ __forceinline__ void cluster_sync_all() {
    asm volatile("barrier.cluster.arrive.aligned;" ::: "memory");
    asm volatile("barrier.cluster.wait.aligned;" ::: "memory");
}
__device__ __forceinline__ float ld_dsmem_f32(uint32_t saddr, uint32_t rank) {
    uint32_t pa; float v;
    asm volatile("mapa.shared::cluster.u32 %0, %1, %2;" : "=r"(pa) : "r"(saddr), "r"(rank));
    asm volatile("ld.shared::cluster.f32 %0, [%1];" : "=f"(v) : "r"(pa) : "memory");
    return v;
}
__device__ __forceinline__ void ldsm_x4(uint32_t& r0, uint32_t& r1, uint32_t& r2,
                                        uint32_t& r3, uint32_t a) {
    asm volatile("ldmatrix.sync.aligned.m8n8.x4.shared.b16 {%0,%1,%2,%3}, [%4];"
                 : "=r"(r0), "=r"(r1), "=r"(r2), "=r"(r3) : "r"(a));
}
__device__ __forceinline__ void mma16816(float* c, const uint32_t* a, uint32_t b0, uint32_t b1) {
    asm volatile("mma.sync.aligned.m16n8k16.row.col.f32.f16.f16.f32 "
                 "{%0,%1,%2,%3},{%4,%5,%6,%7},{%8,%9},{%0,%1,%2,%3};"
                 : "+f"(c[0]), "+f"(c[1]), "+f"(c[2]), "+f"(c[3])
                 : "r"(a[0]), "r"(a[1]), "r"(a[2]), "r"(a[3]), "r"(b0), "r"(b1));
}
__device__ __forceinline__ void cp16(uint32_t s, const void* g) {
    asm volatile("cp.async.cg.shared.global [%0], [%1], 16;" :: "r"(s), "l"(g));
}

// ---------------------------------------------------------------- K0: embed -> fp16
__global__ void __launch_bounds__(256) cvt_kernel(const float* __restrict__ src) {
    int i = blockIdx.x * blockDim.x + threadIdx.x;
    int stride = gridDim.x * blockDim.x;
    const int n4 = (VV * EE) / 4;
    __half2* dst = reinterpret_cast<__half2*>(g_embed16);
    const float4* s4 = reinterpret_cast<const float4*>(src);
    for (; i < n4; i += stride) {
        float4 v = s4[i];
        dst[2 * i + 0] = __floats2half2_rn(v.x, v.y);
        dst[2 * i + 1] = __floats2half2_rn(v.z, v.w);
    }
}

// ---------------------------------------------------------------- K1: Zx
// Zx[tok][j] = sum_k embed[ids[tok]][k] * W1[k][j] + b1[j]
__global__ void __launch_bounds__(128) zx_kernel(const int* __restrict__ ids,
                                                 const float* __restrict__ embed,
                                                 const float* __restrict__ W1,
                                                 const float* __restrict__ b1) {
    __shared__ float xs[32][64];
    __shared__ float ws[64][MIDD];
    __shared__ int   sid[32];
    const int tid = threadIdx.x;
    const int t0  = blockIdx.x * 32;

    if (tid < 32) sid[tid] = ids[t0 + tid];
    __syncthreads();

    float acc[32];
#pragma unroll
    for (int m = 0; m < 32; m++) acc[m] = 0.f;

    for (int kt = 0; kt < 8; kt++) {
        const int k0 = kt * 64;
#pragma unroll
        for (int i = 0; i < 4; i++) {
            int j = tid + i * 128, m = j >> 4, q = j & 15;
            *reinterpret_cast<float4*>(&xs[m][q * 4]) =
                *reinterpret_cast<const float4*>(&embed[(size_t)sid[m] * EE + k0 + q * 4]);
        }
#pragma unroll
        for (int i = 0; i < 16; i++) {
            int j = tid + i * 128, k = j >> 5, q = j & 31;
            *reinterpret_cast<float4*>(&ws[k][q * 4]) =
                *reinterpret_cast<const float4*>(&W1[(size_t)(k0 + k) * MIDD + q * 4]);
        }
        __syncthreads();
#pragma unroll 4
        for (int kk = 0; kk < 64; kk += 4) {
            float w0 = ws[kk + 0][tid], w1 = ws[kk + 1][tid];
            float w2 = ws[kk + 2][tid], w3 = ws[kk + 3][tid];
#pragma unroll
            for (int m = 0; m < 32; m++) {
                float4 x4 = *reinterpret_cast<const float4*>(&xs[m][kk]);
                float a = acc[m];
                a = fmaf(x4.x, w0, a); a = fmaf(x4.y, w1, a);
                a = fmaf(x4.z, w2, a); a = fmaf(x4.w, w3, a);
                acc[m] = a;
            }
        }
        __syncthreads();
    }
    const float bb = b1[tid];
#pragma unroll
    for (int m = 0; m < 32; m++)
        g_Zx[(size_t)(t0 + m) * MIDD + tid] = acc[m] + bb;
}

// ---------------------------------------------------------------- K2: recurrence
// 16 clusters x 4 CTAs (one cluster per batch). 256 thr/CTA.
// warps 0-3 : one W1_h column (this CTA's k-slice) in 128 regs -> partial z
// warps 4-7 : one W2 column (this CTA's n-slice) in 128 regs  -> h_new slice
__global__ void __cluster_dims__(4, 1, 1) __launch_bounds__(256, 1)
rnn_kernel(const float* __restrict__ hidden,
           const float* __restrict__ W1,
           const float* __restrict__ W2) {
    __shared__ __align__(16) float h_loc[128];
    __shared__ __align__(16) float g_s[128];
    __shared__ __align__(16) float zmine[2][128];

    const int tid = threadIdx.x;
    const int b   = blockIdx.x >> 2;
    uint32_t rank;
    asm("mov.u32 %0, %%cluster_ctarank;" : "=r"(rank));

    const int  col = tid & 127;
    const bool isA = (tid < 128);

    float wreg[128];
    if (isA) {
#pragma unroll
        for (int k = 0; k < 128; k++)
            wreg[k] = W1[(size_t)(HH + 128 * rank + k) * MIDD + col];
        h_loc[col] = hidden[(size_t)b * HH + 128 * rank + col];
    } else {
#pragma unroll
        for (int k = 0; k < 128; k++)
            wreg[k] = W2[(size_t)k * EE + 128 * rank + col];
    }
    __syncthreads();

    const float* zx_row  = g_Zx + (size_t)b * SS * MIDD;
    __half*      out_row = g_out16 + (size_t)b * SS * EE + 128 * rank;
    const uint32_t zb = (uint32_t)__cvta_generic_to_shared(&zmine[0][0]);
    float zx_cur = isA ? 0.f : zx_row[col];

    for (int t = 0; t < SS; t++) {
        const int buf = t & 1;
        if (isA) {
            float a0 = 0.f, a1 = 0.f, a2 = 0.f, a3 = 0.f;
#pragma unroll
            for (int k = 0; k < 128; k += 4) {
                float4 h4 = *reinterpret_cast<const float4*>(&h_loc[k]);
                a0 = fmaf(h4.x, wreg[k + 0], a0);
                a1 = fmaf(h4.y, wreg[k + 1], a1);
                a2 = fmaf(h4.z, wreg[k + 2], a2);
                a3 = fmaf(h4.w, wreg[k + 3], a3);
            }
            zmine[buf][col] = (a0 + a1) + (a2 + a3);
        }
        cluster_sync_all();

        if (!isA) {
            // sum partial z across the 4 CTAs + precomputed x-part, gelu
            uint32_t sa = zb + (uint32_t)(buf * 128 + col) * 4u;
            float z = zx_cur;
            z += ld_dsmem_f32(sa, 0);
            z += ld_dsmem_f32(sa, 1);
            z += ld_dsmem_f32(sa, 2);
            z += ld_dsmem_f32(sa, 3);
            g_s[col] = 0.5f * z * (1.0f + erff(z * 0.70710678118f));
            if (t + 1 < SS) zx_cur = zx_row[(t + 1) * MIDD + col];
        }
        __syncthreads();

        if (!isA) {
            float a0 = 0.f, a1 = 0.f, a2 = 0.f, a3 = 0.f;
#pragma unroll
            for (int k = 0; k < 128; k += 4) {
                float4 g4 = *reinterpret_cast<const float4*>(&g_s[k]);
                a0 = fmaf(g4.x, wreg[k + 0], a0);
                a1 = fmaf(g4.y, wreg[k + 1], a1);
                a2 = fmaf(g4.z, wreg[k + 2], a2);
                a3 = fmaf(g4.w, wreg[k + 3], a3);
            }
            float hn = (a0 + a1) + (a2 + a3);
            h_loc[col] = hn;
            out_row[(size_t)t * EE + col] = __float2half_rn(hn);
        }
        __syncthreads();
    }
}

// ---------------------------------------------------------------- K3: classifier GEMM
// C[8192 x 32000] = out16 @ embed16^T + cls_b.  BM=BN=128, BK=32, 256 thr.
#define ASTRIDE 40  // halves per smem row (80B, 16B-aligned, ldmatrix conflict-free)
__global__ void __launch_bounds__(256) gemm_kernel(const float* __restrict__ cls_b,
                                                   float* __restrict__ C) {
    __shared__ __align__(16) __half As[2][128 * ASTRIDE];
    __shared__ __align__(16) __half Bs[2][128 * ASTRIDE];

    const int tid = threadIdx.x;
    const int wid = tid >> 5, lane = tid & 31;
    const int m0 = (blockIdx.x >> 8) * 128;   // 64 m-blocks -> blockIdx.x/256? see launch
    // grid: x = mBlocks*nBlocks flattened as (mb * 250 + nb)
    const int mb = blockIdx.x / 250, nb = blockIdx.x % 250;
    const int M0 = mb * 128, N0 = nb * 128;
    (void)m0;

    const __half* Ag = g_out16  + (size_t)M0 * EE;
    const __half* Bg = g_embed16 + (size_t)N0 * EE;

    const int warp_m = (wid >> 2) * 64;
    const int warp_n = (wid & 3) * 32;

    float c[4][4][4];
#pragma unroll
    for (int i = 0; i < 4; i++)
#pragma unroll
        for (int j = 0; j < 4; j++)
#pragma unroll
            for (int q = 0; q < 4; q++) c[i][j][q] = 0.f;

    const uint32_t asb = (uint32_t)__cvta_generic_to_shared(&As[0][0]);
    const uint32_t bsb = (uint32_t)__cvta_generic_to_shared(&Bs[0][0]);

    auto load_tile = [&](int kt, int buf) {
#pragma unroll
        for (int i = 0; i < 2; i++) {
            int cchunk = tid + i * 256;          // 512 chunks of 16B
            int row = cchunk >> 2, seg = cchunk & 3;
            cp16(asb + (uint32_t)(buf * 128 * ASTRIDE + row * ASTRIDE + seg * 8) * 2,
                 Ag + (size_t)row * EE + kt * 32 + seg * 8);
            cp16(bsb + (uint32_t)(buf * 128 * ASTRIDE + row * ASTRIDE + seg * 8) * 2,
                 Bg + (size_t)row * EE + kt * 32 + seg * 8);
        }
        asm volatile("cp.async.commit_group;");
    };

    load_tile(0, 0);

    for (int kt = 0; kt < 16; kt++) {
        const int buf = kt & 1;
        if (kt + 1 < 16) {
            load_tile(kt + 1, buf ^ 1);
            asm volatile("cp.async.wait_group 1;");
        } else {
            asm volatile("cp.async.wait_group 0;");
        }
        __syncthreads();

#pragma unroll
        for (int kk = 0; kk < 32; kk += 16) {
            uint32_t a[4][4], bfr[4][2];
#pragma unroll
            for (int i = 0; i < 4; i++) {
                uint32_t addr = asb + (uint32_t)(buf * 128 * ASTRIDE +
                               (warp_m + i * 16 + (lane & 15)) * ASTRIDE +
                               kk + ((lane >> 4) << 3)) * 2;
                ldsm_x4(a[i][0], a[i][1], a[i][2], a[i][3], addr);
            }
#pragma unroll
            for (int j2 = 0; j2 < 2; j2++) {
                uint32_t r0, r1, r2, r3;
                uint32_t addr = bsb + (uint32_t)(buf * 128 * ASTRIDE +
                               (warp_n + j2 * 16 + (lane & 15)) * ASTRIDE +
                               kk + ((lane >> 4) << 3)) * 2;
                ldsm_x4(r0, r1, r2, r3, addr);
                bfr[2 * j2 + 0][0] = r0; bfr[2 * j2 + 0][1] = r2;
                bfr[2 * j2 + 1][0] = r1; bfr[2 * j2 + 1][1] = r3;
            }
#pragma unroll
            for (int i = 0; i < 4; i++)
#pragma unroll
                for (int j = 0; j < 4; j++)
                    mma16816(c[i][j], a[i], bfr[j][0], bfr[j][1]);
        }
        __syncthreads();
    }

    // epilogue: + cls_b, fp32 store
#pragma unroll
    for (int i = 0; i < 4; i++) {
        int rm0 = M0 + warp_m + i * 16 + (lane >> 2);
#pragma unroll
        for (int j = 0; j < 4; j++) {
            int gn = N0 + warp_n + j * 8 + (lane & 3) * 2;
            float2 bv = *reinterpret_cast<const float2*>(&cls_b[gn]);
            float2 v0 = make_float2(c[i][j][0] + bv.x, c[i][j][1] + bv.y);
            float2 v1 = make_float2(c[i][j][2] + bv.x, c[i][j][3] + bv.y);
            *reinterpret_cast<float2*>(&C[(size_t)rm0 * VV + gn])       = v0;
            *reinterpret_cast<float2*>(&C[(size_t)(rm0 + 8) * VV + gn]) = v1;
        }
    }
}

// ---------------------------------------------------------------- launch
extern "C" void kernel_launch(void* const* d_in, const int* in_sizes, int n_in,
                              void* d_out, int out_size) {
    const int*   ids    = (const int*)d_in[0];
    const float* hidden = (const float*)d_in[1];
    const float* embed  = (const float*)d_in[2];
    const float* W1     = (const float*)d_in[3];
    const float* b1     = (const float*)d_in[4];
    const float* W2     = (const float*)d_in[5];
    const float* cls_b  = (const float*)d_in[6];
    float* out = (float*)d_out;

    cvt_kernel<<<4096, 256>>>(embed);
    zx_kernel<<<(BB * SS) / 32, 128>>>(ids, embed, W1, b1);
    rnn_kernel<<<BB * 4, 256>>>(hidden, W1, W2);
    gemm_kernel<<<64 * 250, 256>>>(cls_b, out);
}

// round 4
// speedup vs baseline: 1.0467x; 1.0467x over previous
#include <cuda_runtime.h>
#include <cuda_fp16.h>
#include <cstdint>
#include <math.h>

#define VV   32000
#define EE   512
#define HH   512
#define MIDD 128
#define BB   16
#define SS   512

// scratch (device globals: no runtime allocation allowed)
__device__ float  g_Zx[BB * SS * MIDD];     // 4 MB
__device__ __half g_out16[BB * SS * EE];    // 8 MB
__device__ __half g_embed16[VV * EE];       // 32 MB

// ---------------------------------------------------------------- helpers
__device__ __forceinline__ void cluster_sync_all() {
    asm volatile("barrier.cluster.arrive.aligned;" ::: "memory");
    asm volatile("barrier.cluster.wait.aligned;" ::: "memory");
}
__device__ __forceinline__ uint32_t mapa_rank(uint32_t saddr, uint32_t rank) {
    uint32_t pa;
    asm volatile("mapa.shared::cluster.u32 %0, %1, %2;" : "=r"(pa) : "r"(saddr), "r"(rank));
    return pa;
}
__device__ __forceinline__ void st_async_remote(uint32_t daddr, float v, uint32_t dbar) {
    asm volatile("st.async.shared::cluster.mbarrier::complete_tx::bytes.u32 [%0], %1, [%2];"
                 :: "r"(daddr), "r"(__float_as_uint(v)), "r"(dbar) : "memory");
}
__device__ __forceinline__ void mbar_init(uint32_t a, uint32_t cnt) {
    asm volatile("mbarrier.init.shared.b64 [%0], %1;" :: "r"(a), "r"(cnt) : "memory");
}
__device__ __forceinline__ void mbar_expect_tx(uint32_t a, uint32_t bytes) {
    asm volatile("mbarrier.arrive.expect_tx.shared.b64 _, [%0], %1;"
                 :: "r"(a), "r"(bytes) : "memory");
}
__device__ __forceinline__ void mbar_wait(uint32_t a, uint32_t parity) {
    uint32_t done;
    asm volatile("{\n\t.reg .pred p;\n\t"
                 "mbarrier.try_wait.parity.acquire.cta.shared::cta.b64 p, [%1], %2;\n\t"
                 "selp.b32 %0, 1, 0, p;\n\t}"
                 : "=r"(done) : "r"(a), "r"(parity) : "memory");
    if (!done) {
        asm volatile("{\n\t.reg .pred P1;\n\t"
                     "WAIT_LOOP_%=:\n\t"
                     "mbarrier.try_wait.parity.acquire.cta.shared::cta.b64 P1, [%0], %1, 0x989680;\n\t"
                     "@P1 bra.uni WAIT_DONE_%=;\n\t"
                     "bra.uni WAIT_LOOP_%=;\n\t"
                     "WAIT_DONE_%=:\n\t}"
                     :: "r"(a), "r"(parity) : "memory");
    }
}
__device__ __forceinline__ void ldsm_x4(uint32_t& r0, uint32_t& r1, uint32_t& r2,
                                        uint32_t& r3, uint32_t a) {
    asm volatile("ldmatrix.sync.aligned.m8n8.x4.shared.b16 {%0,%1,%2,%3}, [%4];"
                 : "=r"(r0), "=r"(r1), "=r"(r2), "=r"(r3) : "r"(a));
}
__device__ __forceinline__ void mma16816(float* c, const uint32_t* a, uint32_t b0, uint32_t b1) {
    asm volatile("mma.sync.aligned.m16n8k16.row.col.f32.f16.f16.f32 "
                 "{%0,%1,%2,%3},{%4,%5,%6,%7},{%8,%9},{%0,%1,%2,%3};"
                 : "+f"(c[0]), "+f"(c[1]), "+f"(c[2]), "+f"(c[3])
                 : "r"(a[0]), "r"(a[1]), "r"(a[2]), "r"(a[3]), "r"(b0), "r"(b1));
}
__device__ __forceinline__ void cp16(uint32_t s, const void* g) {
    asm volatile("cp.async.cg.shared.global [%0], [%1], 16;" :: "r"(s), "l"(g));
}

// ---------------------------------------------------------------- K0: embed -> fp16
__global__ void __launch_bounds__(256) cvt_kernel(const float* __restrict__ src) {
    int i = blockIdx.x * blockDim.x + threadIdx.x;
    int stride = gridDim.x * blockDim.x;
    const int n4 = (VV * EE) / 4;
    __half2* dst = reinterpret_cast<__half2*>(g_embed16);
    const float4* s4 = reinterpret_cast<const float4*>(src);
    for (; i < n4; i += stride) {
        float4 v = s4[i];
        dst[2 * i + 0] = __floats2half2_rn(v.x, v.y);
        dst[2 * i + 1] = __floats2half2_rn(v.z, v.w);
    }
}

// ---------------------------------------------------------------- K1: Zx
// Zx[tok][j] = sum_k embed[ids[tok]][k] * W1[k][j] + b1[j]
__global__ void __launch_bounds__(128) zx_kernel(const int* __restrict__ ids,
                                                 const float* __restrict__ embed,
                                                 const float* __restrict__ W1,
                                                 const float* __restrict__ b1) {
    __shared__ float xs[32][64];
    __shared__ float ws[64][MIDD];
    __shared__ int   sid[32];
    const int tid = threadIdx.x;
    const int t0  = blockIdx.x * 32;

    if (tid < 32) sid[tid] = ids[t0 + tid];
    __syncthreads();

    float acc[32];
#pragma unroll
    for (int m = 0; m < 32; m++) acc[m] = 0.f;

    for (int kt = 0; kt < 8; kt++) {
        const int k0 = kt * 64;
#pragma unroll
        for (int i = 0; i < 4; i++) {
            int j = tid + i * 128, m = j >> 4, q = j & 15;
            *reinterpret_cast<float4*>(&xs[m][q * 4]) =
                *reinterpret_cast<const float4*>(&embed[(size_t)sid[m] * EE + k0 + q * 4]);
        }
#pragma unroll
        for (int i = 0; i < 16; i++) {
            int j = tid + i * 128, k = j >> 5, q = j & 31;
            *reinterpret_cast<float4*>(&ws[k][q * 4]) =
                *reinterpret_cast<const float4*>(&W1[(size_t)(k0 + k) * MIDD + q * 4]);
        }
        __syncthreads();
#pragma unroll 4
        for (int kk = 0; kk < 64; kk += 4) {
            float w0 = ws[kk + 0][tid], w1 = ws[kk + 1][tid];
            float w2 = ws[kk + 2][tid], w3 = ws[kk + 3][tid];
#pragma unroll
            for (int m = 0; m < 32; m++) {
                float4 x4 = *reinterpret_cast<const float4*>(&xs[m][kk]);
                float a = acc[m];
                a = fmaf(x4.x, w0, a); a = fmaf(x4.y, w1, a);
                a = fmaf(x4.z, w2, a); a = fmaf(x4.w, w3, a);
                acc[m] = a;
            }
        }
        __syncthreads();
    }
    const float bb = b1[tid];
#pragma unroll
    for (int m = 0; m < 32; m++)
        g_Zx[(size_t)(t0 + m) * MIDD + tid] = acc[m] + bb;
}

// ---------------------------------------------------------------- K2: recurrence
// 16 clusters x 4 CTAs (one cluster per batch), 256 thr/CTA.
// Thread (c = tid>>1, half = tid&1):
//   z-phase : partial z[c] over k in [64*half, 64*half+64) of this CTA's h slice
//             (pair-combined via shfl), pushed to all 4 CTAs via st.async + mbarrier.
//   h-phase : h_new[c] (this CTA's n-slice) over the matching 128x128 W2 slice.
// No barrier.cluster in the loop -> no per-step L1D flush.
#define NBUF 4
__global__ void __cluster_dims__(4, 1, 1) __launch_bounds__(256, 1)
rnn_kernel(const float* __restrict__ hidden,
           const float* __restrict__ W1,
           const float* __restrict__ W2) {
    __shared__ __align__(16) float h_loc[128];
    __shared__ __align__(16) float g_s[128];
    __shared__ __align__(16) float zparts[NBUF][4][128];
    __shared__ __align__(8)  unsigned long long mbar[NBUF];

    const int tid  = threadIdx.x;
    const int b    = blockIdx.x >> 2;
    const int c    = tid >> 1;      // output column (0..127)
    const int half = tid & 1;       // k-half (0/1)
    uint32_t rank;
    asm("mov.u32 %0, %%cluster_ctarank;" : "=r"(rank));

    // per-thread weight slices in registers
    float w1z[64], w2h[64];
#pragma unroll
    for (int i = 0; i < 64; i++)
        w1z[i] = W1[(size_t)(HH + 128 * rank + 64 * half + i) * MIDD + c];
#pragma unroll
    for (int i = 0; i < 64; i++)
        w2h[i] = W2[(size_t)(64 * half + i) * EE + 128 * rank + c];

    const uint32_t zp_loc  = (uint32_t)__cvta_generic_to_shared(&zparts[0][0][0]);
    const uint32_t bar_loc = (uint32_t)__cvta_generic_to_shared(&mbar[0]);

    if (tid == 0) {
#pragma unroll
        for (int s = 0; s < NBUF; s++) mbar_init(bar_loc + 8u * s, 1);
    }
    if (tid < 128) h_loc[tid] = hidden[(size_t)b * HH + 128 * rank + tid];
    __syncthreads();
    cluster_sync_all();   // barriers + h visible before any remote st.async

    // mapa'd bases for the 4 destination CTAs
    uint32_t zp_dst[4], bar_dst[4];
#pragma unroll
    for (int r = 0; r < 4; r++) {
        zp_dst[r]  = mapa_rank(zp_loc, r);
        bar_dst[r] = mapa_rank(bar_loc, r);
    }

    const float* zx_row  = g_Zx    + (size_t)b * SS * MIDD;
    __half*      out_row = g_out16 + (size_t)b * SS * EE + 128 * rank;
    float zx_cur = (tid < 128) ? zx_row[tid] : 0.f;

    for (int t = 0; t < SS; t++) {
        const int buf = t & (NBUF - 1);
        const uint32_t ph = (uint32_t)((t >> 2) & 1);

        if (tid == 0) mbar_expect_tx(bar_loc + 8u * buf, 4 * 128 * 4);

        // ---- z partial over local h slice
        float a0 = 0.f, a1 = 0.f, a2 = 0.f, a3 = 0.f;
#pragma unroll
        for (int i = 0; i < 64; i += 4) {
            float4 h4 = *reinterpret_cast<const float4*>(&h_loc[64 * half + i]);
            a0 = fmaf(h4.x, w1z[i + 0], a0);
            a1 = fmaf(h4.y, w1z[i + 1], a1);
            a2 = fmaf(h4.z, w1z[i + 2], a2);
            a3 = fmaf(h4.w, w1z[i + 3], a3);
        }
        float part = (a0 + a1) + (a2 + a3);
        part += __shfl_xor_sync(0xffffffffu, part, 1);

        if (half == 0) {
            const uint32_t off = (uint32_t)((buf * 4 + rank) * 128 + c) * 4u;
#pragma unroll
            for (int r = 0; r < 4; r++)
                st_async_remote(zp_dst[r] + off, part, bar_dst[r] + 8u * buf);
        }

        mbar_wait(bar_loc + 8u * buf, ph);

        if (tid < 128) {
            const float* zp = &zparts[buf][0][tid];
            float z = zx_cur + ((zp[0] + zp[128]) + (zp[256] + zp[384]));
            g_s[tid] = 0.5f * z * (1.0f + erff(z * 0.70710678118f));
            if (t + 1 < SS) zx_cur = zx_row[(size_t)(t + 1) * MIDD + tid];
        }
        __syncthreads();

        // ---- h_new slice
        float b0 = 0.f, b1a = 0.f, b2 = 0.f, b3 = 0.f;
#pragma unroll
        for (int i = 0; i < 64; i += 4) {
            float4 g4 = *reinterpret_cast<const float4*>(&g_s[64 * half + i]);
            b0  = fmaf(g4.x, w2h[i + 0], b0);
            b1a = fmaf(g4.y, w2h[i + 1], b1a);
            b2  = fmaf(g4.z, w2h[i + 2], b2);
            b3  = fmaf(g4.w, w2h[i + 3], b3);
        }
        float hp = (b0 + b1a) + (b2 + b3);
        hp += __shfl_xor_sync(0xffffffffu, hp, 1);
        if (half == 0) {
            h_loc[c] = hp;
            out_row[(size_t)t * EE + c] = __float2half_rn(hp);
        }
        __syncthreads();
    }
    cluster_sync_all();   // no CTA exits while peers may still st.async into it
}

// ---------------------------------------------------------------- K3: classifier GEMM
// C[8192 x 32000] = out16 @ embed16^T + cls_b.  BM=BN=128, BK=32, 256 thr.
#define ASTRIDE 40  // halves per smem row (80B, 16B-aligned, ldmatrix conflict-free)
__global__ void __launch_bounds__(256) gemm_kernel(const float* __restrict__ cls_b,
                                                   float* __restrict__ C) {
    __shared__ __align__(16) __half As[2][128 * ASTRIDE];
    __shared__ __align__(16) __half Bs[2][128 * ASTRIDE];

    const int tid = threadIdx.x;
    const int wid = tid >> 5, lane = tid & 31;
    const int mb = blockIdx.x / 250, nb = blockIdx.x % 250;
    const int M0 = mb * 128, N0 = nb * 128;

    const __half* Ag = g_out16   + (size_t)M0 * EE;
    const __half* Bg = g_embed16 + (size_t)N0 * EE;

    const int warp_m = (wid >> 2) * 64;
    const int warp_n = (wid & 3) * 32;

    float c[4][4][4];
#pragma unroll
    for (int i = 0; i < 4; i++)
#pragma unroll
        for (int j = 0; j < 4; j++)
#pragma unroll
            for (int q = 0; q < 4; q++) c[i][j][q] = 0.f;

    const uint32_t asb = (uint32_t)__cvta_generic_to_shared(&As[0][0]);
    const uint32_t bsb = (uint32_t)__cvta_generic_to_shared(&Bs[0][0]);

    auto load_tile = [&](int kt, int buf) {
#pragma unroll
        for (int i = 0; i < 2; i++) {
            int cchunk = tid + i * 256;          // 512 chunks of 16B
            int row = cchunk >> 2, seg = cchunk & 3;
            cp16(asb + (uint32_t)(buf * 128 * ASTRIDE + row * ASTRIDE + seg * 8) * 2,
                 Ag + (size_t)row * EE + kt * 32 + seg * 8);
            cp16(bsb + (uint32_t)(buf * 128 * ASTRIDE + row * ASTRIDE + seg * 8) * 2,
                 Bg + (size_t)row * EE + kt * 32 + seg * 8);
        }
        asm volatile("cp.async.commit_group;");
    };

    load_tile(0, 0);

    for (int kt = 0; kt < 16; kt++) {
        const int buf = kt & 1;
        if (kt + 1 < 16) {
            load_tile(kt + 1, buf ^ 1);
            asm volatile("cp.async.wait_group 1;");
        } else {
            asm volatile("cp.async.wait_group 0;");
        }
        __syncthreads();

#pragma unroll
        for (int kk = 0; kk < 32; kk += 16) {
            uint32_t a[4][4], bfr[4][2];
#pragma unroll
            for (int i = 0; i < 4; i++) {
                uint32_t addr = asb + (uint32_t)(buf * 128 * ASTRIDE +
                               (warp_m + i * 16 + (lane & 15)) * ASTRIDE +
                               kk + ((lane >> 4) << 3)) * 2;
                ldsm_x4(a[i][0], a[i][1], a[i][2], a[i][3], addr);
            }
#pragma unroll
            for (int j2 = 0; j2 < 2; j2++) {
                uint32_t r0, r1, r2, r3;
                uint32_t addr = bsb + (uint32_t)(buf * 128 * ASTRIDE +
                               (warp_n + j2 * 16 + (lane & 15)) * ASTRIDE +
                               kk + ((lane >> 4) << 3)) * 2;
                ldsm_x4(r0, r1, r2, r3, addr);
                bfr[2 * j2 + 0][0] = r0; bfr[2 * j2 + 0][1] = r2;
                bfr[2 * j2 + 1][0] = r1; bfr[2 * j2 + 1][1] = r3;
            }
#pragma unroll
            for (int i = 0; i < 4; i++)
#pragma unroll
                for (int j = 0; j < 4; j++)
                    mma16816(c[i][j], a[i], bfr[j][0], bfr[j][1]);
        }
        __syncthreads();
    }

    // epilogue: + cls_b, fp32 store
#pragma unroll
    for (int i = 0; i < 4; i++) {
        int rm0 = M0 + warp_m + i * 16 + (lane >> 2);
#pragma unroll
        for (int j = 0; j < 4; j++) {
            int gn = N0 + warp_n + j * 8 + (lane & 3) * 2;
            float2 bv = *reinterpret_cast<const float2*>(&cls_b[gn]);
            float2 v0 = make_float2(c[i][j][0] + bv.x, c[i][j][1] + bv.y);
            float2 v1 = make_float2(c[i][j][2] + bv.x, c[i][j][3] + bv.y);
            *reinterpret_cast<float2*>(&C[(size_t)rm0 * VV + gn])       = v0;
            *reinterpret_cast<float2*>(&C[(size_t)(rm0 + 8) * VV + gn]) = v1;
        }
    }
}

// ---------------------------------------------------------------- launch
extern "C" void kernel_launch(void* const* d_in, const int* in_sizes, int n_in,
                              void* d_out, int out_size) {
    const int*   ids    = (const int*)d_in[0];
    const float* hidden = (const float*)d_in[1];
    const float* embed  = (const float*)d_in[2];
    const float* W1     = (const float*)d_in[3];
    const float* b1     = (const float*)d_in[4];
    const float* W2     = (const float*)d_in[5];
    const float* cls_b  = (const float*)d_in[6];
    float* out = (float*)d_out;

    cvt_kernel<<<4096, 256>>>(embed);
    zx_kernel<<<(BB * SS) / 32, 128>>>(ids, embed, W1, b1);
    rnn_kernel<<<BB * 4, 256>>>(hidden, W1, W2);
    gemm_kernel<<<64 * 250, 256>>>(cls_b, out);
}

// round 6
// speedup vs baseline: 1.0626x; 1.0151x over previous
#include <cuda_runtime.h>
#include <cuda_fp16.h>
#include <cstdint>
#include <math.h>

#define VV   32000
#define EE   512
#define HH   512
#define MIDD 128
#define BB   16
#define SS   512

// scratch (device globals: no runtime allocation allowed)
__device__ float  g_Zx[BB * SS * MIDD];     // 4 MB
__device__ __half g_out16[BB * SS * EE];    // 8 MB
__device__ __half g_embed16[VV * EE];       // 32 MB

// ---------------------------------------------------------------- helpers
__device__ __forceinline__ void cluster_sync_all() {
    asm volatile("barrier.cluster.arrive.aligned;" ::: "memory");
    asm volatile("barrier.cluster.wait.aligned;" ::: "memory");
}
__device__ __forceinline__ uint32_t mapa_rank(uint32_t saddr, uint32_t rank) {
    uint32_t pa;
    asm volatile("mapa.shared::cluster.u32 %0, %1, %2;" : "=r"(pa) : "r"(saddr), "r"(rank));
    return pa;
}
__device__ __forceinline__ void st_async_remote(uint32_t daddr, float v, uint32_t dbar) {
    asm volatile("st.async.shared::cluster.mbarrier::complete_tx::bytes.u32 [%0], %1, [%2];"
                 :: "r"(daddr), "r"(__float_as_uint(v)), "r"(dbar) : "memory");
}
__device__ __forceinline__ void mbar_init(uint32_t a, uint32_t cnt) {
    asm volatile("mbarrier.init.shared.b64 [%0], %1;" :: "r"(a), "r"(cnt) : "memory");
}
__device__ __forceinline__ void mbar_expect_tx(uint32_t a, uint32_t bytes) {
    asm volatile("mbarrier.arrive.expect_tx.shared.b64 _, [%0], %1;"
                 :: "r"(a), "r"(bytes) : "memory");
}
__device__ __forceinline__ void mbar_wait(uint32_t a, uint32_t parity) {
    uint32_t done;
    asm volatile("{\n\t.reg .pred p;\n\t"
                 "mbarrier.try_wait.parity.acquire.cta.shared::cta.b64 p, [%1], %2;\n\t"
                 "selp.b32 %0, 1, 0, p;\n\t}"
                 : "=r"(done) : "r"(a), "r"(parity) : "memory");
    if (!done) {
        asm volatile("{\n\t.reg .pred P1;\n\t"
                     "WAIT_LOOP_%=:\n\t"
                     "mbarrier.try_wait.parity.acquire.cta.shared::cta.b64 P1, [%0], %1, 0x989680;\n\t"
                     "@P1 bra.uni WAIT_DONE_%=;\n\t"
                     "bra.uni WAIT_LOOP_%=;\n\t"
                     "WAIT_DONE_%=:\n\t}"
                     :: "r"(a), "r"(parity) : "memory");
    }
}
__device__ __forceinline__ void ldsm_x4(uint32_t& r0, uint32_t& r1, uint32_t& r2,
                                        uint32_t& r3, uint32_t a) {
    asm volatile("ldmatrix.sync.aligned.m8n8.x4.shared.b16 {%0,%1,%2,%3}, [%4];"
                 : "=r"(r0), "=r"(r1), "=r"(r2), "=r"(r3) : "r"(a));
}
__device__ __forceinline__ void mma16816(float* c, const uint32_t* a, uint32_t b0, uint32_t b1) {
    asm volatile("mma.sync.aligned.m16n8k16.row.col.f32.f16.f16.f32 "
                 "{%0,%1,%2,%3},{%4,%5,%6,%7},{%8,%9},{%0,%1,%2,%3};"
                 : "+f"(c[0]), "+f"(c[1]), "+f"(c[2]), "+f"(c[3])
                 : "r"(a[0]), "r"(a[1]), "r"(a[2]), "r"(a[3]), "r"(b0), "r"(b1));
}
__device__ __forceinline__ void cp16(uint32_t s, const void* g) {
    asm volatile("cp.async.cg.shared.global [%0], [%1], 16;" :: "r"(s), "l"(g));
}

// ---------------------------------------------------------------- K0: embed -> fp16
__global__ void __launch_bounds__(256) cvt_kernel(const float* __restrict__ src) {
    int i = blockIdx.x * blockDim.x + threadIdx.x;
    int stride = gridDim.x * blockDim.x;
    const int n4 = (VV * EE) / 4;
    __half2* dst = reinterpret_cast<__half2*>(g_embed16);
    const float4* s4 = reinterpret_cast<const float4*>(src);
    for (; i < n4; i += stride) {
        float4 v = s4[i];
        dst[2 * i + 0] = __floats2half2_rn(v.x, v.y);
        dst[2 * i + 1] = __floats2half2_rn(v.z, v.w);
    }
}

// ---------------------------------------------------------------- K1: Zx
__global__ void __launch_bounds__(128) zx_kernel(const int* __restrict__ ids,
                                                 const float* __restrict__ embed,
                                                 const float* __restrict__ W1,
                                                 const float* __restrict__ b1) {
    __shared__ float xs[32][64];
    __shared__ float ws[64][MIDD];
    __shared__ int   sid[32];
    const int tid = threadIdx.x;
    const int t0  = blockIdx.x * 32;

    if (tid < 32) sid[tid] = ids[t0 + tid];
    __syncthreads();

    float acc[32];
#pragma unroll
    for (int m = 0; m < 32; m++) acc[m] = 0.f;

    for (int kt = 0; kt < 8; kt++) {
        const int k0 = kt * 64;
#pragma unroll
        for (int i = 0; i < 4; i++) {
            int j = tid + i * 128, m = j >> 4, q = j & 15;
            *reinterpret_cast<float4*>(&xs[m][q * 4]) =
                *reinterpret_cast<const float4*>(&embed[(size_t)sid[m] * EE + k0 + q * 4]);
        }
#pragma unroll
        for (int i = 0; i < 16; i++) {
            int j = tid + i * 128, k = j >> 5, q = j & 31;
            *reinterpret_cast<float4*>(&ws[k][q * 4]) =
                *reinterpret_cast<const float4*>(&W1[(size_t)(k0 + k) * MIDD + q * 4]);
        }
        __syncthreads();
#pragma unroll 4
        for (int kk = 0; kk < 64; kk += 4) {
            float w0 = ws[kk + 0][tid], w1 = ws[kk + 1][tid];
            float w2 = ws[kk + 2][tid], w3 = ws[kk + 3][tid];
#pragma unroll
            for (int m = 0; m < 32; m++) {
                float4 x4 = *reinterpret_cast<const float4*>(&xs[m][kk]);
                float a = acc[m];
                a = fmaf(x4.x, w0, a); a = fmaf(x4.y, w1, a);
                a = fmaf(x4.z, w2, a); a = fmaf(x4.w, w3, a);
                acc[m] = a;
            }
        }
        __syncthreads();
    }
    const float bb = b1[tid];
#pragma unroll
    for (int m = 0; m < 32; m++)
        g_Zx[(size_t)(t0 + m) * MIDD + tid] = acc[m] + bb;
}

// ---------------------------------------------------------------- K2: recurrence (R4-passing version)
#define NBUF 4
__global__ void __cluster_dims__(4, 1, 1) __launch_bounds__(256, 1)
rnn_kernel(const float* __restrict__ hidden,
           const float* __restrict__ W1,
           const float* __restrict__ W2) {
    __shared__ __align__(16) float h_loc[128];
    __shared__ __align__(16) float g_s[128];
    __shared__ __align__(16) float zparts[NBUF][4][128];
    __shared__ __align__(8)  unsigned long long mbar[NBUF];

    const int tid  = threadIdx.x;
    const int b    = blockIdx.x >> 2;
    const int c    = tid >> 1;
    const int half = tid & 1;
    uint32_t rank;
    asm("mov.u32 %0, %%cluster_ctarank;" : "=r"(rank));

    float w1z[64], w2h[64];
#pragma unroll
    for (int i = 0; i < 64; i++)
        w1z[i] = W1[(size_t)(HH + 128 * rank + 64 * half + i) * MIDD + c];
#pragma unroll
    for (int i = 0; i < 64; i++)
        w2h[i] = W2[(size_t)(64 * half + i) * EE + 128 * rank + c];

    const uint32_t zp_loc  = (uint32_t)__cvta_generic_to_shared(&zparts[0][0][0]);
    const uint32_t bar_loc = (uint32_t)__cvta_generic_to_shared(&mbar[0]);

    if (tid == 0) {
#pragma unroll
        for (int s = 0; s < NBUF; s++) mbar_init(bar_loc + 8u * s, 1);
    }
    if (tid < 128) h_loc[tid] = hidden[(size_t)b * HH + 128 * rank + tid];
    __syncthreads();
    cluster_sync_all();

    uint32_t zp_dst[4], bar_dst[4];
#pragma unroll
    for (int r = 0; r < 4; r++) {
        zp_dst[r]  = mapa_rank(zp_loc, r);
        bar_dst[r] = mapa_rank(bar_loc, r);
    }

    const float* zx_row  = g_Zx    + (size_t)b * SS * MIDD;
    __half*      out_row = g_out16 + (size_t)b * SS * EE + 128 * rank;
    float zx_cur = (tid < 128) ? zx_row[tid] : 0.f;

    for (int t = 0; t < SS; t++) {
        const int buf = t & (NBUF - 1);
        const uint32_t ph = (uint32_t)((t >> 2) & 1);

        if (tid == 0) mbar_expect_tx(bar_loc + 8u * buf, 4 * 128 * 4);

        float a0 = 0.f, a1 = 0.f, a2 = 0.f, a3 = 0.f;
#pragma unroll
        for (int i = 0; i < 64; i += 4) {
            float4 h4 = *reinterpret_cast<const float4*>(&h_loc[64 * half + i]);
            a0 = fmaf(h4.x, w1z[i + 0], a0);
            a1 = fmaf(h4.y, w1z[i + 1], a1);
            a2 = fmaf(h4.z, w1z[i + 2], a2);
            a3 = fmaf(h4.w, w1z[i + 3], a3);
        }
        float part = (a0 + a1) + (a2 + a3);
        part += __shfl_xor_sync(0xffffffffu, part, 1);

        if (half == 0) {
            const uint32_t off = (uint32_t)((buf * 4 + rank) * 128 + c) * 4u;
#pragma unroll
            for (int r = 0; r < 4; r++)
                st_async_remote(zp_dst[r] + off, part, bar_dst[r] + 8u * buf);
        }

        mbar_wait(bar_loc + 8u * buf, ph);

        if (tid < 128) {
            const float* zp = &zparts[buf][0][tid];
            float z = zx_cur + ((zp[0] + zp[128]) + (zp[256] + zp[384]));
            g_s[tid] = 0.5f * z * (1.0f + erff(z * 0.70710678118f));
            if (t + 1 < SS) zx_cur = zx_row[(size_t)(t + 1) * MIDD + tid];
        }
        __syncthreads();

        float b0 = 0.f, b1a = 0.f, b2 = 0.f, b3 = 0.f;
#pragma unroll
        for (int i = 0; i < 64; i += 4) {
            float4 g4 = *reinterpret_cast<const float4*>(&g_s[64 * half + i]);
            b0  = fmaf(g4.x, w2h[i + 0], b0);
            b1a = fmaf(g4.y, w2h[i + 1], b1a);
            b2  = fmaf(g4.z, w2h[i + 2], b2);
            b3  = fmaf(g4.w, w2h[i + 3], b3);
        }
        float hp = (b0 + b1a) + (b2 + b3);
        hp += __shfl_xor_sync(0xffffffffu, hp, 1);
        if (half == 0) {
            h_loc[c] = hp;
            out_row[(size_t)t * EE + c] = __float2half_rn(hp);
        }
        __syncthreads();
    }
    cluster_sync_all();
}

// ---------------------------------------------------------------- K3: classifier GEMM (mma.sync, big tiles)
// C[8192 x 32000] = out16 @ embed16^T + cls_b
// BM=128, BN=256, BK=32, 256 thr (8 warps, warp tile 64x64), 3-stage cp.async.
#define ASTRIDE 40                      // halves per smem row (80B)
#define A_ST    (128 * ASTRIDE)         // halves per A stage
#define B_ST    (256 * ASTRIDE)         // halves per B stage
#define GSMEM   ((3 * (A_ST + B_ST)) * 2)   // 92160 B

__global__ void __launch_bounds__(256, 1) gemm_kernel(const float* __restrict__ cls_b,
                                                      float* __restrict__ C) {
    extern __shared__ __align__(16) __half sm[];
    __half* As = sm;
    __half* Bs = sm + 3 * A_ST;

    const int tid = threadIdx.x;
    const int wid = tid >> 5, lane = tid & 31;
    const int mb = blockIdx.x / 125, nb = blockIdx.x % 125;
    const int M0 = mb * 128, N0 = nb * 256;

    const __half* Ag = g_out16   + (size_t)M0 * EE;
    const __half* Bg = g_embed16 + (size_t)N0 * EE;

    const int warp_m = (wid >> 2) * 64;   // 0 or 64
    const int warp_n = (wid & 3) * 64;    // 0,64,128,192

    float c[4][8][4];
#pragma unroll
    for (int i = 0; i < 4; i++)
#pragma unroll
        for (int j = 0; j < 8; j++)
#pragma unroll
            for (int q = 0; q < 4; q++) c[i][j][q] = 0.f;

    const uint32_t asb = (uint32_t)__cvta_generic_to_shared(As);
    const uint32_t bsb = (uint32_t)__cvta_generic_to_shared(Bs);

    auto load_tile = [&](int kt, int st) {
        const uint32_t ab = asb + (uint32_t)(st * A_ST) * 2;
        const uint32_t bb = bsb + (uint32_t)(st * B_ST) * 2;
#pragma unroll
        for (int i = 0; i < 2; i++) {           // A: 512 chunks
            int cc = tid + i * 256;
            int r = cc >> 2, sg = cc & 3;
            cp16(ab + (uint32_t)(r * ASTRIDE + sg * 8) * 2,
                 Ag + (size_t)r * EE + kt * 32 + sg * 8);
        }
#pragma unroll
        for (int i = 0; i < 4; i++) {           // B: 1024 chunks
            int cc = tid + i * 256;
            int r = cc >> 2, sg = cc & 3;
            cp16(bb + (uint32_t)(r * ASTRIDE + sg * 8) * 2,
                 Bg + (size_t)r * EE + kt * 32 + sg * 8);
        }
        asm volatile("cp.async.commit_group;");
    };

    load_tile(0, 0);
    load_tile(1, 1);

    for (int kt = 0; kt < 16; kt++) {
        const int st = kt % 3;
        if (kt < 15) asm volatile("cp.async.wait_group 1;");
        else         asm volatile("cp.async.wait_group 0;");
        __syncthreads();

        if (kt + 2 < 16) load_tile(kt + 2, (kt + 2) % 3);

        const uint32_t ab = asb + (uint32_t)(st * A_ST) * 2;
        const uint32_t bb = bsb + (uint32_t)(st * B_ST) * 2;

#pragma unroll
        for (int kk = 0; kk < 32; kk += 16) {
            uint32_t a[4][4], bfr[8][2];
#pragma unroll
            for (int i = 0; i < 4; i++) {
                uint32_t addr = ab + (uint32_t)((warp_m + i * 16 + (lane & 15)) * ASTRIDE +
                                                kk + ((lane >> 4) << 3)) * 2;
                ldsm_x4(a[i][0], a[i][1], a[i][2], a[i][3], addr);
            }
#pragma unroll
            for (int j2 = 0; j2 < 4; j2++) {
                uint32_t r0, r1, r2, r3;
                uint32_t addr = bb + (uint32_t)((warp_n + j2 * 16 + (lane & 15)) * ASTRIDE +
                                                kk + ((lane >> 4) << 3)) * 2;
                ldsm_x4(r0, r1, r2, r3, addr);
                bfr[2 * j2 + 0][0] = r0; bfr[2 * j2 + 0][1] = r2;
                bfr[2 * j2 + 1][0] = r1; bfr[2 * j2 + 1][1] = r3;
            }
#pragma unroll
            for (int i = 0; i < 4; i++)
#pragma unroll
                for (int j = 0; j < 8; j++)
                    mma16816(c[i][j], a[i], bfr[j][0], bfr[j][1]);
        }
        __syncthreads();
    }

    // epilogue: + cls_b, fp32 store
#pragma unroll
    for (int i = 0; i < 4; i++) {
        int rm0 = M0 + warp_m + i * 16 + (lane >> 2);
#pragma unroll
        for (int j = 0; j < 8; j++) {
            int gn = N0 + warp_n + j * 8 + (lane & 3) * 2;
            float2 bv = *reinterpret_cast<const float2*>(&cls_b[gn]);
            float2 v0 = make_float2(c[i][j][0] + bv.x, c[i][j][1] + bv.y);
            float2 v1 = make_float2(c[i][j][2] + bv.x, c[i][j][3] + bv.y);
            *reinterpret_cast<float2*>(&C[(size_t)rm0 * VV + gn])       = v0;
            *reinterpret_cast<float2*>(&C[(size_t)(rm0 + 8) * VV + gn]) = v1;
        }
    }
}

// ---------------------------------------------------------------- launch
extern "C" void kernel_launch(void* const* d_in, const int* in_sizes, int n_in,
                              void* d_out, int out_size) {
    const int*   ids    = (const int*)d_in[0];
    const float* hidden = (const float*)d_in[1];
    const float* embed  = (const float*)d_in[2];
    const float* W1     = (const float*)d_in[3];
    const float* b1     = (const float*)d_in[4];
    const float* W2     = (const float*)d_in[5];
    const float* cls_b  = (const float*)d_in[6];
    float* out = (float*)d_out;

    cudaFuncSetAttribute(gemm_kernel, cudaFuncAttributeMaxDynamicSharedMemorySize, GSMEM);

    cvt_kernel<<<4096, 256>>>(embed);
    zx_kernel<<<(BB * SS) / 32, 128>>>(ids, embed, W1, b1);
    rnn_kernel<<<BB * 4, 256>>>(hidden, W1, W2);
    gemm_kernel<<<64 * 125, 256, GSMEM>>>(cls_b, out);
}

// round 7
// speedup vs baseline: 1.1070x; 1.0418x over previous
#include <cuda_runtime.h>
#include <cuda_fp16.h>
#include <cstdint>
#include <math.h>

#define VV   32000
#define EE   512
#define HH   512
#define MIDD 128
#define BB   16
#define SS   512

// scratch (device globals: no runtime allocation allowed)
__device__ float  g_Zx[BB * SS * MIDD];     // 4 MB
__device__ __half g_out16[BB * SS * EE];    // 8 MB
__device__ __half g_embed16[VV * EE];       // 32 MB
__device__ float  g_h[BB * HH];             // persisted RNN state between chunks

// ---------------------------------------------------------------- helpers
__device__ __forceinline__ void cluster_sync_all() {
    asm volatile("barrier.cluster.arrive.aligned;" ::: "memory");
    asm volatile("barrier.cluster.wait.aligned;" ::: "memory");
}
__device__ __forceinline__ uint32_t mapa_rank(uint32_t saddr, uint32_t rank) {
    uint32_t pa;
    asm volatile("mapa.shared::cluster.u32 %0, %1, %2;" : "=r"(pa) : "r"(saddr), "r"(rank));
    return pa;
}
__device__ __forceinline__ void st_async_remote(uint32_t daddr, float v, uint32_t dbar) {
    asm volatile("st.async.shared::cluster.mbarrier::complete_tx::bytes.u32 [%0], %1, [%2];"
                 :: "r"(daddr), "r"(__float_as_uint(v)), "r"(dbar) : "memory");
}
__device__ __forceinline__ void mbar_init(uint32_t a, uint32_t cnt) {
    asm volatile("mbarrier.init.shared.b64 [%0], %1;" :: "r"(a), "r"(cnt) : "memory");
}
__device__ __forceinline__ void mbar_expect_tx(uint32_t a, uint32_t bytes) {
    asm volatile("mbarrier.arrive.expect_tx.shared.b64 _, [%0], %1;"
                 :: "r"(a), "r"(bytes) : "memory");
}
__device__ __forceinline__ void mbar_wait(uint32_t a, uint32_t parity) {
    uint32_t done;
    asm volatile("{\n\t.reg .pred p;\n\t"
                 "mbarrier.try_wait.parity.acquire.cta.shared::cta.b64 p, [%1], %2;\n\t"
                 "selp.b32 %0, 1, 0, p;\n\t}"
                 : "=r"(done) : "r"(a), "r"(parity) : "memory");
    if (!done) {
        asm volatile("{\n\t.reg .pred P1;\n\t"
                     "WAIT_LOOP_%=:\n\t"
                     "mbarrier.try_wait.parity.acquire.cta.shared::cta.b64 P1, [%0], %1, 0x989680;\n\t"
                     "@P1 bra.uni WAIT_DONE_%=;\n\t"
                     "bra.uni WAIT_LOOP_%=;\n\t"
                     "WAIT_DONE_%=:\n\t}"
                     :: "r"(a), "r"(parity) : "memory");
    }
}
__device__ __forceinline__ void ldsm_x4(uint32_t& r0, uint32_t& r1, uint32_t& r2,
                                        uint32_t& r3, uint32_t a) {
    asm volatile("ldmatrix.sync.aligned.m8n8.x4.shared.b16 {%0,%1,%2,%3}, [%4];"
                 : "=r"(r0), "=r"(r1), "=r"(r2), "=r"(r3) : "r"(a));
}
__device__ __forceinline__ void mma16816(float* c, const uint32_t* a, uint32_t b0, uint32_t b1) {
    asm volatile("mma.sync.aligned.m16n8k16.row.col.f32.f16.f16.f32 "
                 "{%0,%1,%2,%3},{%4,%5,%6,%7},{%8,%9},{%0,%1,%2,%3};"
                 : "+f"(c[0]), "+f"(c[1]), "+f"(c[2]), "+f"(c[3])
                 : "r"(a[0]), "r"(a[1]), "r"(a[2]), "r"(a[3]), "r"(b0), "r"(b1));
}
__device__ __forceinline__ void cp16(uint32_t s, const void* g) {
    asm volatile("cp.async.cg.shared.global [%0], [%1], 16;" :: "r"(s), "l"(g));
}

// ---------------------------------------------------------------- K0: embed -> fp16
__global__ void __launch_bounds__(256) cvt_kernel(const float* __restrict__ src) {
    int i = blockIdx.x * blockDim.x + threadIdx.x;
    int stride = gridDim.x * blockDim.x;
    const int n4 = (VV * EE) / 4;
    __half2* dst = reinterpret_cast<__half2*>(g_embed16);
    const float4* s4 = reinterpret_cast<const float4*>(src);
    for (; i < n4; i += stride) {
        float4 v = s4[i];
        dst[2 * i + 0] = __floats2half2_rn(v.x, v.y);
        dst[2 * i + 1] = __floats2half2_rn(v.z, v.w);
    }
}

// ---------------------------------------------------------------- K1: Zx
__global__ void __launch_bounds__(128) zx_kernel(const int* __restrict__ ids,
                                                 const float* __restrict__ embed,
                                                 const float* __restrict__ W1,
                                                 const float* __restrict__ b1) {
    __shared__ float xs[32][64];
    __shared__ float ws[64][MIDD];
    __shared__ int   sid[32];
    const int tid = threadIdx.x;
    const int t0  = blockIdx.x * 32;

    if (tid < 32) sid[tid] = ids[t0 + tid];
    __syncthreads();

    float acc[32];
#pragma unroll
    for (int m = 0; m < 32; m++) acc[m] = 0.f;

    for (int kt = 0; kt < 8; kt++) {
        const int k0 = kt * 64;
#pragma unroll
        for (int i = 0; i < 4; i++) {
            int j = tid + i * 128, m = j >> 4, q = j & 15;
            *reinterpret_cast<float4*>(&xs[m][q * 4]) =
                *reinterpret_cast<const float4*>(&embed[(size_t)sid[m] * EE + k0 + q * 4]);
        }
#pragma unroll
        for (int i = 0; i < 16; i++) {
            int j = tid + i * 128, k = j >> 5, q = j & 31;
            *reinterpret_cast<float4*>(&ws[k][q * 4]) =
                *reinterpret_cast<const float4*>(&W1[(size_t)(k0 + k) * MIDD + q * 4]);
        }
        __syncthreads();
#pragma unroll 4
        for (int kk = 0; kk < 64; kk += 4) {
            float w0 = ws[kk + 0][tid], w1 = ws[kk + 1][tid];
            float w2 = ws[kk + 2][tid], w3 = ws[kk + 3][tid];
#pragma unroll
            for (int m = 0; m < 32; m++) {
                float4 x4 = *reinterpret_cast<const float4*>(&xs[m][kk]);
                float a = acc[m];
                a = fmaf(x4.x, w0, a); a = fmaf(x4.y, w1, a);
                a = fmaf(x4.z, w2, a); a = fmaf(x4.w, w3, a);
                acc[m] = a;
            }
        }
        __syncthreads();
    }
    const float bb = b1[tid];
#pragma unroll
    for (int m = 0; m < 32; m++)
        g_Zx[(size_t)(t0 + m) * MIDD + tid] = acc[m] + bb;
}

// ---------------------------------------------------------------- rnn chunk body (128 steps)
#define NBUF   4
#define TCHUNK 128
__device__ __forceinline__ void rnn_body(const float* __restrict__ hidden,
                                         const float* __restrict__ W1,
                                         const float* __restrict__ W2,
                                         int chunk) {
    __shared__ __align__(16) float h_loc[128];
    __shared__ __align__(16) float g_s[128];
    __shared__ __align__(16) float zparts[NBUF][4][128];
    __shared__ __align__(8)  unsigned long long mbar[NBUF];

    const int tid  = threadIdx.x;
    const int b    = blockIdx.x >> 2;
    const int c    = tid >> 1;
    const int half = tid & 1;
    const int t0   = chunk * TCHUNK;
    uint32_t rank;
    asm("mov.u32 %0, %%cluster_ctarank;" : "=r"(rank));

    float w1z[64], w2h[64];
#pragma unroll
    for (int i = 0; i < 64; i++)
        w1z[i] = W1[(size_t)(HH + 128 * rank + 64 * half + i) * MIDD + c];
#pragma unroll
    for (int i = 0; i < 64; i++)
        w2h[i] = W2[(size_t)(64 * half + i) * EE + 128 * rank + c];

    const uint32_t zp_loc  = (uint32_t)__cvta_generic_to_shared(&zparts[0][0][0]);
    const uint32_t bar_loc = (uint32_t)__cvta_generic_to_shared(&mbar[0]);

    if (tid == 0) {
#pragma unroll
        for (int s = 0; s < NBUF; s++) mbar_init(bar_loc + 8u * s, 1);
    }
    if (tid < 128) {
        h_loc[tid] = (chunk == 0) ? hidden[(size_t)b * HH + 128 * rank + tid]
                                  : g_h[(size_t)b * HH + 128 * rank + tid];
    }
    __syncthreads();
    cluster_sync_all();

    uint32_t zp_dst[4], bar_dst[4];
#pragma unroll
    for (int r = 0; r < 4; r++) {
        zp_dst[r]  = mapa_rank(zp_loc, r);
        bar_dst[r] = mapa_rank(bar_loc, r);
    }

    const float* zx_row  = g_Zx    + (size_t)b * SS * MIDD;
    __half*      out_row = g_out16 + (size_t)b * SS * EE + (size_t)t0 * EE + 128 * rank;
    float zx_cur = (tid < 128) ? zx_row[(size_t)t0 * MIDD + tid] : 0.f;

    for (int t = 0; t < TCHUNK; t++) {
        const int buf = t & (NBUF - 1);
        const uint32_t ph = (uint32_t)((t >> 2) & 1);

        if (tid == 0) mbar_expect_tx(bar_loc + 8u * buf, 4 * 128 * 4);

        float a0 = 0.f, a1 = 0.f, a2 = 0.f, a3 = 0.f;
#pragma unroll
        for (int i = 0; i < 64; i += 4) {
            float4 h4 = *reinterpret_cast<const float4*>(&h_loc[64 * half + i]);
            a0 = fmaf(h4.x, w1z[i + 0], a0);
            a1 = fmaf(h4.y, w1z[i + 1], a1);
            a2 = fmaf(h4.z, w1z[i + 2], a2);
            a3 = fmaf(h4.w, w1z[i + 3], a3);
        }
        float part = (a0 + a1) + (a2 + a3);
        part += __shfl_xor_sync(0xffffffffu, part, 1);

        if (half == 0) {
            const uint32_t off = (uint32_t)((buf * 4 + rank) * 128 + c) * 4u;
#pragma unroll
            for (int r = 0; r < 4; r++)
                st_async_remote(zp_dst[r] + off, part, bar_dst[r] + 8u * buf);
        }

        mbar_wait(bar_loc + 8u * buf, ph);

        if (tid < 128) {
            const float* zp = &zparts[buf][0][tid];
            float z = zx_cur + ((zp[0] + zp[128]) + (zp[256] + zp[384]));
            g_s[tid] = 0.5f * z * (1.0f + erff(z * 0.70710678118f));
            if (t + 1 < TCHUNK) zx_cur = zx_row[(size_t)(t0 + t + 1) * MIDD + tid];
        }
        __syncthreads();

        float b0 = 0.f, b1a = 0.f, b2 = 0.f, b3 = 0.f;
#pragma unroll
        for (int i = 0; i < 64; i += 4) {
            float4 g4 = *reinterpret_cast<const float4*>(&g_s[64 * half + i]);
            b0  = fmaf(g4.x, w2h[i + 0], b0);
            b1a = fmaf(g4.y, w2h[i + 1], b1a);
            b2  = fmaf(g4.z, w2h[i + 2], b2);
            b3  = fmaf(g4.w, w2h[i + 3], b3);
        }
        float hp = (b0 + b1a) + (b2 + b3);
        hp += __shfl_xor_sync(0xffffffffu, hp, 1);
        if (half == 0) {
            h_loc[c] = hp;
            out_row[(size_t)t * EE + c] = __float2half_rn(hp);
        }
        __syncthreads();
    }

    // persist h for next chunk
    if (tid < 128) g_h[(size_t)b * HH + 128 * rank + tid] = h_loc[tid];
    cluster_sync_all();
}

// ---------------------------------------------------------------- gemm chunk body
// One chunk = 2000 blocks: b (0..15) x nb (0..124); rows = b*512 + chunk*128 .. +128
#define ASTRIDE 40
#define A_ST    (128 * ASTRIDE)
#define B_ST    (256 * ASTRIDE)
#define GSMEM   ((3 * (A_ST + B_ST)) * 2)   // 92160 B

__device__ __forceinline__ void gemm_body(const float* __restrict__ cls_b,
                                          float* __restrict__ C,
                                          int gb, int chunk) {
    extern __shared__ __align__(16) __half sm[];
    __half* As = sm;
    __half* Bs = sm + 3 * A_ST;

    const int tid = threadIdx.x;
    const int wid = tid >> 5, lane = tid & 31;
    const int bidx = gb / 125, nb = gb % 125;
    const int R0 = bidx * SS + chunk * 128;     // first output row
    const int N0 = nb * 256;

    const __half* Ag = g_out16   + (size_t)R0 * EE;
    const __half* Bg = g_embed16 + (size_t)N0 * EE;

    const int warp_m = (wid >> 2) * 64;
    const int warp_n = (wid & 3) * 64;

    float c[4][8][4];
#pragma unroll
    for (int i = 0; i < 4; i++)
#pragma unroll
        for (int j = 0; j < 8; j++)
#pragma unroll
            for (int q = 0; q < 4; q++) c[i][j][q] = 0.f;

    const uint32_t asb = (uint32_t)__cvta_generic_to_shared(As);
    const uint32_t bsb = (uint32_t)__cvta_generic_to_shared(Bs);

    auto load_tile = [&](int kt, int st) {
        const uint32_t ab = asb + (uint32_t)(st * A_ST) * 2;
        const uint32_t bb = bsb + (uint32_t)(st * B_ST) * 2;
#pragma unroll
        for (int i = 0; i < 2; i++) {
            int cc = tid + i * 256;
            int r = cc >> 2, sg = cc & 3;
            cp16(ab + (uint32_t)(r * ASTRIDE + sg * 8) * 2,
                 Ag + (size_t)r * EE + kt * 32 + sg * 8);
        }
#pragma unroll
        for (int i = 0; i < 4; i++) {
            int cc = tid + i * 256;
            int r = cc >> 2, sg = cc & 3;
            cp16(bb + (uint32_t)(r * ASTRIDE + sg * 8) * 2,
                 Bg + (size_t)r * EE + kt * 32 + sg * 8);
        }
        asm volatile("cp.async.commit_group;");
    };

    load_tile(0, 0);
    load_tile(1, 1);

    for (int kt = 0; kt < 16; kt++) {
        const int st = kt % 3;
        if (kt < 15) asm volatile("cp.async.wait_group 1;");
        else         asm volatile("cp.async.wait_group 0;");
        __syncthreads();

        if (kt + 2 < 16) load_tile(kt + 2, (kt + 2) % 3);

        const uint32_t ab = asb + (uint32_t)(st * A_ST) * 2;
        const uint32_t bb = bsb + (uint32_t)(st * B_ST) * 2;

#pragma unroll
        for (int kk = 0; kk < 32; kk += 16) {
            uint32_t a[4][4], bfr[8][2];
#pragma unroll
            for (int i = 0; i < 4; i++) {
                uint32_t addr = ab + (uint32_t)((warp_m + i * 16 + (lane & 15)) * ASTRIDE +
                                                kk + ((lane >> 4) << 3)) * 2;
                ldsm_x4(a[i][0], a[i][1], a[i][2], a[i][3], addr);
            }
#pragma unroll
            for (int j2 = 0; j2 < 4; j2++) {
                uint32_t r0, r1, r2, r3;
                uint32_t addr = bb + (uint32_t)((warp_n + j2 * 16 + (lane & 15)) * ASTRIDE +
                                                kk + ((lane >> 4) << 3)) * 2;
                ldsm_x4(r0, r1, r2, r3, addr);
                bfr[2 * j2 + 0][0] = r0; bfr[2 * j2 + 0][1] = r2;
                bfr[2 * j2 + 1][0] = r1; bfr[2 * j2 + 1][1] = r3;
            }
#pragma unroll
            for (int i = 0; i < 4; i++)
#pragma unroll
                for (int j = 0; j < 8; j++)
                    mma16816(c[i][j], a[i], bfr[j][0], bfr[j][1]);
        }
        __syncthreads();
    }

#pragma unroll
    for (int i = 0; i < 4; i++) {
        int rm0 = R0 + warp_m + i * 16 + (lane >> 2);
#pragma unroll
        for (int j = 0; j < 8; j++) {
            int gn = N0 + warp_n + j * 8 + (lane & 3) * 2;
            float2 bv = *reinterpret_cast<const float2*>(&cls_b[gn]);
            float2 v0 = make_float2(c[i][j][0] + bv.x, c[i][j][1] + bv.y);
            float2 v1 = make_float2(c[i][j][2] + bv.x, c[i][j][3] + bv.y);
            *reinterpret_cast<float2*>(&C[(size_t)rm0 * VV + gn])       = v0;
            *reinterpret_cast<float2*>(&C[(size_t)(rm0 + 8) * VV + gn]) = v1;
        }
    }
}

// ---------------------------------------------------------------- fused phase kernel
// bids [0, n_rnn) -> rnn chunk `rnn_chunk`; bids [n_rnn, ...) -> gemm chunk `gemm_chunk`.
// rnn occupies whole clusters (n_rnn = 64 = 16 clusters); gemm CTAs never touch cluster ops.
__global__ void __cluster_dims__(4, 1, 1) __launch_bounds__(256, 1)
phase_kernel(const float* __restrict__ hidden,
             const float* __restrict__ W1,
             const float* __restrict__ W2,
             const float* __restrict__ cls_b,
             float* __restrict__ C,
             int n_rnn, int rnn_chunk, int gemm_chunk) {
    if ((int)blockIdx.x < n_rnn) {
        rnn_body(hidden, W1, W2, rnn_chunk);
    } else if (gemm_chunk >= 0) {
        gemm_body(cls_b, C, (int)blockIdx.x - n_rnn, gemm_chunk);
    }
}

// ---------------------------------------------------------------- launch
extern "C" void kernel_launch(void* const* d_in, const int* in_sizes, int n_in,
                              void* d_out, int out_size) {
    const int*   ids    = (const int*)d_in[0];
    const float* hidden = (const float*)d_in[1];
    const float* embed  = (const float*)d_in[2];
    const float* W1     = (const float*)d_in[3];
    const float* b1     = (const float*)d_in[4];
    const float* W2     = (const float*)d_in[5];
    const float* cls_b  = (const float*)d_in[6];
    float* out = (float*)d_out;

    cudaFuncSetAttribute(phase_kernel, cudaFuncAttributeMaxDynamicSharedMemorySize, GSMEM);

    cvt_kernel<<<4096, 256>>>(embed);
    zx_kernel<<<(BB * SS) / 32, 128>>>(ids, embed, W1, b1);

    // P0: rnn chunk 0 alone
    phase_kernel<<<64, 256, GSMEM>>>(hidden, W1, W2, cls_b, out, 64, 0, -1);
    // P1..P3: rnn chunk c overlapped with gemm chunk c-1
    phase_kernel<<<2064, 256, GSMEM>>>(hidden, W1, W2, cls_b, out, 64, 1, 0);
    phase_kernel<<<2064, 256, GSMEM>>>(hidden, W1, W2, cls_b, out, 64, 2, 1);
    phase_kernel<<<2064, 256, GSMEM>>>(hidden, W1, W2, cls_b, out, 64, 3, 2);
    // P4: last gemm chunk
    phase_kernel<<<2000, 256, GSMEM>>>(hidden, W1, W2, cls_b, out, 0, -1, 3);
}

// round 8
// speedup vs baseline: 1.2190x; 1.1012x over previous
#include <cuda_runtime.h>
#include <cuda_fp16.h>
#include <cstdint>
#include <math.h>

#define VV   32000
#define EE   512
#define HH   512
#define MIDD 128
#define BB   16
#define SS   512

// scratch (device globals: no runtime allocation allowed)
__device__ float  g_Zx[BB * SS * MIDD];     // 4 MB
__device__ __half g_out16[BB * SS * EE];    // 8 MB
__device__ __half g_embed16[VV * EE];       // 32 MB
__device__ float  g_h[BB * HH];             // persisted RNN state between chunks

// ---------------------------------------------------------------- helpers
__device__ __forceinline__ void cluster_sync_all() {
    asm volatile("barrier.cluster.arrive.aligned;" ::: "memory");
    asm volatile("barrier.cluster.wait.aligned;" ::: "memory");
}
__device__ __forceinline__ uint32_t mapa_rank(uint32_t saddr, uint32_t rank) {
    uint32_t pa;
    asm volatile("mapa.shared::cluster.u32 %0, %1, %2;" : "=r"(pa) : "r"(saddr), "r"(rank));
    return pa;
}
__device__ __forceinline__ void st_async_remote(uint32_t daddr, float v, uint32_t dbar) {
    asm volatile("st.async.shared::cluster.mbarrier::complete_tx::bytes.u32 [%0], %1, [%2];"
                 :: "r"(daddr), "r"(__float_as_uint(v)), "r"(dbar) : "memory");
}
__device__ __forceinline__ void mbar_init(uint32_t a, uint32_t cnt) {
    asm volatile("mbarrier.init.shared.b64 [%0], %1;" :: "r"(a), "r"(cnt) : "memory");
}
__device__ __forceinline__ void mbar_expect_tx(uint32_t a, uint32_t bytes) {
    asm volatile("mbarrier.arrive.expect_tx.shared.b64 _, [%0], %1;"
                 :: "r"(a), "r"(bytes) : "memory");
}
__device__ __forceinline__ void mbar_wait(uint32_t a, uint32_t parity) {
    uint32_t done;
    asm volatile("{\n\t.reg .pred p;\n\t"
                 "mbarrier.try_wait.parity.acquire.cta.shared::cta.b64 p, [%1], %2;\n\t"
                 "selp.b32 %0, 1, 0, p;\n\t}"
                 : "=r"(done) : "r"(a), "r"(parity) : "memory");
    if (!done) {
        asm volatile("{\n\t.reg .pred P1;\n\t"
                     "WAIT_LOOP_%=:\n\t"
                     "mbarrier.try_wait.parity.acquire.cta.shared::cta.b64 P1, [%0], %1, 0x989680;\n\t"
                     "@P1 bra.uni WAIT_DONE_%=;\n\t"
                     "bra.uni WAIT_LOOP_%=;\n\t"
                     "WAIT_DONE_%=:\n\t}"
                     :: "r"(a), "r"(parity) : "memory");
    }
}
__device__ __forceinline__ void ldsm_x4(uint32_t& r0, uint32_t& r1, uint32_t& r2,
                                        uint32_t& r3, uint32_t a) {
    asm volatile("ldmatrix.sync.aligned.m8n8.x4.shared.b16 {%0,%1,%2,%3}, [%4];"
                 : "=r"(r0), "=r"(r1), "=r"(r2), "=r"(r3) : "r"(a));
}
__device__ __forceinline__ void mma16816(float* c, const uint32_t* a, uint32_t b0, uint32_t b1) {
    asm volatile("mma.sync.aligned.m16n8k16.row.col.f32.f16.f16.f32 "
                 "{%0,%1,%2,%3},{%4,%5,%6,%7},{%8,%9},{%0,%1,%2,%3};"
                 : "+f"(c[0]), "+f"(c[1]), "+f"(c[2]), "+f"(c[3])
                 : "r"(a[0]), "r"(a[1]), "r"(a[2]), "r"(a[3]), "r"(b0), "r"(b1));
}
__device__ __forceinline__ void cp16(uint32_t s, const void* g) {
    asm volatile("cp.async.cg.shared.global [%0], [%1], 16;" :: "r"(s), "l"(g));
}

// ---------------------------------------------------------------- K0: embed -> fp16
__global__ void __launch_bounds__(256) cvt_kernel(const float* __restrict__ src) {
    int i = blockIdx.x * blockDim.x + threadIdx.x;
    int stride = gridDim.x * blockDim.x;
    const int n4 = (VV * EE) / 4;
    __half2* dst = reinterpret_cast<__half2*>(g_embed16);
    const float4* s4 = reinterpret_cast<const float4*>(src);
    for (; i < n4; i += stride) {
        float4 v = s4[i];
        dst[2 * i + 0] = __floats2half2_rn(v.x, v.y);
        dst[2 * i + 1] = __floats2half2_rn(v.z, v.w);
    }
}

// ---------------------------------------------------------------- K1: Zx
__global__ void __launch_bounds__(128) zx_kernel(const int* __restrict__ ids,
                                                 const float* __restrict__ embed,
                                                 const float* __restrict__ W1,
                                                 const float* __restrict__ b1) {
    __shared__ float xs[32][64];
    __shared__ float ws[64][MIDD];
    __shared__ int   sid[32];
    const int tid = threadIdx.x;
    const int t0  = blockIdx.x * 32;

    if (tid < 32) sid[tid] = ids[t0 + tid];
    __syncthreads();

    float acc[32];
#pragma unroll
    for (int m = 0; m < 32; m++) acc[m] = 0.f;

    for (int kt = 0; kt < 8; kt++) {
        const int k0 = kt * 64;
#pragma unroll
        for (int i = 0; i < 4; i++) {
            int j = tid + i * 128, m = j >> 4, q = j & 15;
            *reinterpret_cast<float4*>(&xs[m][q * 4]) =
                *reinterpret_cast<const float4*>(&embed[(size_t)sid[m] * EE + k0 + q * 4]);
        }
#pragma unroll
        for (int i = 0; i < 16; i++) {
            int j = tid + i * 128, k = j >> 5, q = j & 31;
            *reinterpret_cast<float4*>(&ws[k][q * 4]) =
                *reinterpret_cast<const float4*>(&W1[(size_t)(k0 + k) * MIDD + q * 4]);
        }
        __syncthreads();
#pragma unroll 4
        for (int kk = 0; kk < 64; kk += 4) {
            float w0 = ws[kk + 0][tid], w1 = ws[kk + 1][tid];
            float w2 = ws[kk + 2][tid], w3 = ws[kk + 3][tid];
#pragma unroll
            for (int m = 0; m < 32; m++) {
                float4 x4 = *reinterpret_cast<const float4*>(&xs[m][kk]);
                float a = acc[m];
                a = fmaf(x4.x, w0, a); a = fmaf(x4.y, w1, a);
                a = fmaf(x4.z, w2, a); a = fmaf(x4.w, w3, a);
                acc[m] = a;
            }
        }
        __syncthreads();
    }
    const float bb = b1[tid];
#pragma unroll
    for (int m = 0; m < 32; m++)
        g_Zx[(size_t)(t0 + m) * MIDD + tid] = acc[m] + bb;
}

// ---------------------------------------------------------------- rnn chunk body (128 steps)
#define NBUF   4
#define TCHUNK 128
__device__ __forceinline__ void rnn_body(const float* __restrict__ hidden,
                                         const float* __restrict__ W1,
                                         const float* __restrict__ W2,
                                         int chunk) {
    __shared__ __align__(16) float h_loc[128];
    __shared__ __align__(16) float g_s[128];
    __shared__ __align__(16) float zparts[NBUF][4][128];
    __shared__ __align__(8)  unsigned long long mbar[NBUF];

    const int tid  = threadIdx.x;
    const int b    = blockIdx.x >> 2;
    const int c    = tid >> 1;
    const int half = tid & 1;
    const int t0   = chunk * TCHUNK;
    uint32_t rank;
    asm("mov.u32 %0, %%cluster_ctarank;" : "=r"(rank));

    float w1z[64], w2h[64];
#pragma unroll
    for (int i = 0; i < 64; i++)
        w1z[i] = W1[(size_t)(HH + 128 * rank + 64 * half + i) * MIDD + c];
#pragma unroll
    for (int i = 0; i < 64; i++)
        w2h[i] = W2[(size_t)(64 * half + i) * EE + 128 * rank + c];

    const uint32_t zp_loc  = (uint32_t)__cvta_generic_to_shared(&zparts[0][0][0]);
    const uint32_t bar_loc = (uint32_t)__cvta_generic_to_shared(&mbar[0]);

    if (tid == 0) {
#pragma unroll
        for (int s = 0; s < NBUF; s++) mbar_init(bar_loc + 8u * s, 1);
    }
    if (tid < 128) {
        h_loc[tid] = (chunk == 0) ? hidden[(size_t)b * HH + 128 * rank + tid]
                                  : g_h[(size_t)b * HH + 128 * rank + tid];
    }
    __syncthreads();
    cluster_sync_all();

    uint32_t zp_dst[4], bar_dst[4];
#pragma unroll
    for (int r = 0; r < 4; r++) {
        zp_dst[r]  = mapa_rank(zp_loc, r);
        bar_dst[r] = mapa_rank(bar_loc, r);
    }

    const float* zx_row  = g_Zx    + (size_t)b * SS * MIDD;
    __half*      out_row = g_out16 + (size_t)b * SS * EE + (size_t)t0 * EE + 128 * rank;
    float zx_cur = (tid < 128) ? zx_row[(size_t)t0 * MIDD + tid] : 0.f;

    for (int t = 0; t < TCHUNK; t++) {
        const int buf = t & (NBUF - 1);
        const uint32_t ph = (uint32_t)((t >> 2) & 1);

        if (tid == 0) mbar_expect_tx(bar_loc + 8u * buf, 4 * 128 * 4);

        float a0 = 0.f, a1 = 0.f, a2 = 0.f, a3 = 0.f;
#pragma unroll
        for (int i = 0; i < 64; i += 4) {
            float4 h4 = *reinterpret_cast<const float4*>(&h_loc[64 * half + i]);
            a0 = fmaf(h4.x, w1z[i + 0], a0);
            a1 = fmaf(h4.y, w1z[i + 1], a1);
            a2 = fmaf(h4.z, w1z[i + 2], a2);
            a3 = fmaf(h4.w, w1z[i + 3], a3);
        }
        float part = (a0 + a1) + (a2 + a3);
        part += __shfl_xor_sync(0xffffffffu, part, 1);

        if (half == 0) {
            const uint32_t off = (uint32_t)((buf * 4 + rank) * 128 + c) * 4u;
#pragma unroll
            for (int r = 0; r < 4; r++)
                st_async_remote(zp_dst[r] + off, part, bar_dst[r] + 8u * buf);
        }

        mbar_wait(bar_loc + 8u * buf, ph);

        if (tid < 128) {
            const float* zp = &zparts[buf][0][tid];
            float z = zx_cur + ((zp[0] + zp[128]) + (zp[256] + zp[384]));
            g_s[tid] = 0.5f * z * (1.0f + erff(z * 0.70710678118f));
            if (t + 1 < TCHUNK) zx_cur = zx_row[(size_t)(t0 + t + 1) * MIDD + tid];
        }
        __syncthreads();

        float b0 = 0.f, b1a = 0.f, b2 = 0.f, b3 = 0.f;
#pragma unroll
        for (int i = 0; i < 64; i += 4) {
            float4 g4 = *reinterpret_cast<const float4*>(&g_s[64 * half + i]);
            b0  = fmaf(g4.x, w2h[i + 0], b0);
            b1a = fmaf(g4.y, w2h[i + 1], b1a);
            b2  = fmaf(g4.z, w2h[i + 2], b2);
            b3  = fmaf(g4.w, w2h[i + 3], b3);
        }
        float hp = (b0 + b1a) + (b2 + b3);
        hp += __shfl_xor_sync(0xffffffffu, hp, 1);
        if (half == 0) {
            h_loc[c] = hp;
            out_row[(size_t)t * EE + c] = __float2half_rn(hp);
        }
        __syncthreads();
    }

    if (tid < 128) g_h[(size_t)b * HH + 128 * rank + tid] = h_loc[tid];
    cluster_sync_all();
}

// ---------------------------------------------------------------- gemm chunk body
// BM=128, BN=256, BK=64, 3 stages, 256 thr, warp tile 64x64, frag double-buffer.
#define ASTRIDE 72                       // halves per smem row (144B)
#define A_ST    (128 * ASTRIDE)
#define B_ST    (256 * ASTRIDE)
#define GSMEM   ((3 * (A_ST + B_ST)) * 2)   // 165888 B

__device__ __forceinline__ void gemm_body(const float* __restrict__ cls_b,
                                          float* __restrict__ C,
                                          int gb, int chunk) {
    extern __shared__ __align__(16) __half sm[];
    __half* As = sm;
    __half* Bs = sm + 3 * A_ST;

    const int tid = threadIdx.x;
    const int wid = tid >> 5, lane = tid & 31;
    const int bidx = gb / 125, nb = gb % 125;
    const int R0 = bidx * SS + chunk * 128;
    const int N0 = nb * 256;

    const __half* Ag = g_out16   + (size_t)R0 * EE;
    const __half* Bg = g_embed16 + (size_t)N0 * EE;

    const int warp_m = (wid >> 2) * 64;
    const int warp_n = (wid & 3) * 64;

    float c[4][8][4];
#pragma unroll
    for (int i = 0; i < 4; i++)
#pragma unroll
        for (int j = 0; j < 8; j++)
#pragma unroll
            for (int q = 0; q < 4; q++) c[i][j][q] = 0.f;

    const uint32_t asb = (uint32_t)__cvta_generic_to_shared(As);
    const uint32_t bsb = (uint32_t)__cvta_generic_to_shared(Bs);

    auto load_tile = [&](int kt, int st) {
        const uint32_t ab = asb + (uint32_t)(st * A_ST) * 2;
        const uint32_t bb = bsb + (uint32_t)(st * B_ST) * 2;
#pragma unroll
        for (int i = 0; i < 4; i++) {           // A: 1024 chunks of 16B
            int cc = tid + i * 256;
            int r = cc >> 3, sg = cc & 7;
            cp16(ab + (uint32_t)(r * ASTRIDE + sg * 8) * 2,
                 Ag + (size_t)r * EE + kt * 64 + sg * 8);
        }
#pragma unroll
        for (int i = 0; i < 8; i++) {           // B: 2048 chunks of 16B
            int cc = tid + i * 256;
            int r = cc >> 3, sg = cc & 7;
            cp16(bb + (uint32_t)(r * ASTRIDE + sg * 8) * 2,
                 Bg + (size_t)r * EE + kt * 64 + sg * 8);
        }
        asm volatile("cp.async.commit_group;");
    };

    uint32_t afr[2][4][4], bfr[2][8][2];

    auto ldsm_batch = [&](int kk, uint32_t ab, uint32_t bb, int pb) {
        const uint32_t koff = (uint32_t)(kk * 16 + ((lane >> 4) << 3));
#pragma unroll
        for (int i = 0; i < 4; i++) {
            uint32_t addr = ab + (uint32_t)((warp_m + i * 16 + (lane & 15)) * ASTRIDE + koff) * 2;
            ldsm_x4(afr[pb][i][0], afr[pb][i][1], afr[pb][i][2], afr[pb][i][3], addr);
        }
#pragma unroll
        for (int j2 = 0; j2 < 4; j2++) {
            uint32_t r0, r1, r2, r3;
            uint32_t addr = bb + (uint32_t)((warp_n + j2 * 16 + (lane & 15)) * ASTRIDE + koff) * 2;
            ldsm_x4(r0, r1, r2, r3, addr);
            bfr[pb][2 * j2 + 0][0] = r0; bfr[pb][2 * j2 + 0][1] = r2;
            bfr[pb][2 * j2 + 1][0] = r1; bfr[pb][2 * j2 + 1][1] = r3;
        }
    };

    load_tile(0, 0);
    load_tile(1, 1);

    for (int kt = 0; kt < 8; kt++) {
        const int st = kt % 3;
        if (kt < 7) asm volatile("cp.async.wait_group 1;");
        else        asm volatile("cp.async.wait_group 0;");
        __syncthreads();

        if (kt + 2 < 8) load_tile(kt + 2, (kt + 2) % 3);

        const uint32_t ab = asb + (uint32_t)(st * A_ST) * 2;
        const uint32_t bb = bsb + (uint32_t)(st * B_ST) * 2;

        ldsm_batch(0, ab, bb, 0);
#pragma unroll
        for (int kk = 0; kk < 4; kk++) {
            const int cur = kk & 1;
            if (kk < 3) ldsm_batch(kk + 1, ab, bb, cur ^ 1);
#pragma unroll
            for (int i = 0; i < 4; i++)
#pragma unroll
                for (int j = 0; j < 8; j++)
                    mma16816(c[i][j], afr[cur][i], bfr[cur][j][0], bfr[cur][j][1]);
        }
    }

#pragma unroll
    for (int i = 0; i < 4; i++) {
        int rm0 = R0 + warp_m + i * 16 + (lane >> 2);
#pragma unroll
        for (int j = 0; j < 8; j++) {
            int gn = N0 + warp_n + j * 8 + (lane & 3) * 2;
            float2 bv = *reinterpret_cast<const float2*>(&cls_b[gn]);
            float2 v0 = make_float2(c[i][j][0] + bv.x, c[i][j][1] + bv.y);
            float2 v1 = make_float2(c[i][j][2] + bv.x, c[i][j][3] + bv.y);
            *reinterpret_cast<float2*>(&C[(size_t)rm0 * VV + gn])       = v0;
            *reinterpret_cast<float2*>(&C[(size_t)(rm0 + 8) * VV + gn]) = v1;
        }
    }
}

// ---------------------------------------------------------------- fused phase kernel
__global__ void __cluster_dims__(4, 1, 1) __launch_bounds__(256, 1)
phase_kernel(const float* __restrict__ hidden,
             const float* __restrict__ W1,
             const float* __restrict__ W2,
             const float* __restrict__ cls_b,
             float* __restrict__ C,
             int n_rnn, int rnn_chunk, int gemm_chunk) {
    if ((int)blockIdx.x < n_rnn) {
        rnn_body(hidden, W1, W2, rnn_chunk);
    } else if (gemm_chunk >= 0) {
        gemm_body(cls_b, C, (int)blockIdx.x - n_rnn, gemm_chunk);
    }
}

// ---------------------------------------------------------------- launch
extern "C" void kernel_launch(void* const* d_in, const int* in_sizes, int n_in,
                              void* d_out, int out_size) {
    const int*   ids    = (const int*)d_in[0];
    const float* hidden = (const float*)d_in[1];
    const float* embed  = (const float*)d_in[2];
    const float* W1     = (const float*)d_in[3];
    const float* b1     = (const float*)d_in[4];
    const float* W2     = (const float*)d_in[5];
    const float* cls_b  = (const float*)d_in[6];
    float* out = (float*)d_out;

    cudaFuncSetAttribute(phase_kernel, cudaFuncAttributeMaxDynamicSharedMemorySize, GSMEM);

    cvt_kernel<<<4096, 256>>>(embed);
    zx_kernel<<<(BB * SS) / 32, 128>>>(ids, embed, W1, b1);

    phase_kernel<<<64, 256, GSMEM>>>(hidden, W1, W2, cls_b, out, 64, 0, -1);
    phase_kernel<<<2064, 256, GSMEM>>>(hidden, W1, W2, cls_b, out, 64, 1, 0);
    phase_kernel<<<2064, 256, GSMEM>>>(hidden, W1, W2, cls_b, out, 64, 2, 1);
    phase_kernel<<<2064, 256, GSMEM>>>(hidden, W1, W2, cls_b, out, 64, 3, 2);
    phase_kernel<<<2000, 256, GSMEM>>>(hidden, W1, W2, cls_b, out, 0, -1, 3);
}